// round 3
// baseline (speedup 1.0000x reference)
#include <cuda_runtime.h>
#include <cstdint>
#include <cstddef>

#define DIMC 192
#define NB   8
#define NTOK 4096
#define BR   128
#define BC   64
#define NTHREADS 256
#define SCALE 0.07216878364870322f   /* 192^-0.5 */

// fragment-major smem sizes (floats)
#define SQF_SZ (8*24*32*4)    /* 24576: [warp][kc][lane][4 slots] */
#define SKF_SZ (24*4*32*4)    /* 12288: [kc][npair][lane][4 slots] */
#define SVF_SZ (8*12*32*4)    /* 12288: [key-chunk][col-pair][lane][4 slots] */
#define SMEM_FLOATS (SQF_SZ + SKF_SZ + SVF_SZ + 128 + 128)
#define SMEM_BYTES  (SMEM_FLOATS * 4)

__device__ __forceinline__ float f2tff(float f) {
    uint32_t u;
    asm("cvt.rna.tf32.f32 %0, %1;" : "=r"(u) : "f"(f));
    return __uint_as_float(u);
}
__device__ __forceinline__ float sqrt_approx(float x) {
    float r;
    asm("sqrt.approx.f32 %0, %1;" : "=f"(r) : "f"(x));
    return r;
}
__device__ __forceinline__ uint32_t fu(float f) { return __float_as_uint(f); }

__device__ __forceinline__ void mma8(float* c,
        uint32_t a0, uint32_t a1, uint32_t a2, uint32_t a3,
        uint32_t b0, uint32_t b1) {
    asm volatile("mma.sync.aligned.m16n8k8.row.col.f32.tf32.tf32.f32 "
        "{%0,%1,%2,%3}, {%4,%5,%6,%7}, {%8,%9}, {%0,%1,%2,%3};"
        : "+f"(c[0]), "+f"(c[1]), "+f"(c[2]), "+f"(c[3])
        : "r"(a0), "r"(a1), "r"(a2), "r"(a3), "r"(b0), "r"(b1));
}

__global__ void __launch_bounds__(NTHREADS, 1)
qkv_l2attn_kernel(const float* __restrict__ qkv, float* __restrict__ out)
{
    extern __shared__ float sm[];
    float* sQf = sm;
    float* sKf = sQf + SQF_SZ;
    float* sVf = sKf + SKF_SZ;
    float* sQ2 = sVf + SVF_SZ;     // 128
    float* sK2 = sQ2 + 128;        // 2 x 64 (double-buffered)

    const int tid  = threadIdx.x;
    const int warp = tid >> 5;
    const int lane = tid & 31;
    const int g    = lane >> 2;
    const int t4   = lane & 3;

    const int b  = blockIdx.y;
    const int q0 = blockIdx.x * BR;

    // ---- zero reduction buffers ----
    if (tid < 128) sQ2[tid] = 0.f; else sK2[tid - 128] = 0.f;
    __syncthreads();

    // ---- load Q tile into fragment-major smem (scaled, tf32) + q^2 ----
    const float* qptr = qkv + ((size_t)b * NTOK + q0) * (3 * DIMC);
    for (int idx = tid * 4; idx < BR * DIMC; idx += NTHREADS * 4) {
        int r = idx / DIMC, c = idx - r * DIMC;
        float4 v = *(const float4*)(qptr + (size_t)r * (3 * DIMC) + c);
        float x0 = f2tff(v.x * SCALE), x1 = f2tff(v.y * SCALE);
        float x2 = f2tff(v.z * SCALE), x3 = f2tff(v.w * SCALE);
        int w = r >> 4, rr = r & 15, gq = rr & 7, hi = rr >> 3;
        int kc = c >> 3, chalf = (c >> 2) & 1, s = hi + (chalf << 1);
        int swz = kc & 7;
        float* bp = sQf + (w * 24 + kc) * 128 + s;
        int L = gq << 2;
        bp[((L + 0) ^ swz) << 2] = x0;
        bp[((L + 1) ^ swz) << 2] = x1;
        bp[((L + 2) ^ swz) << 2] = x2;
        bp[((L + 3) ^ swz) << 2] = x3;
        float part = x0*x0 + x1*x1 + x2*x2 + x3*x3;
        part += __shfl_xor_sync(0xffffffffu, part, 1);
        part += __shfl_xor_sync(0xffffffffu, part, 2);
        if ((lane & 3) == 0) atomicAdd(&sQ2[r], part);   // quad spans one row (192%16==0)
    }
    __syncthreads();

    const int r0 = warp * 16 + g;
    const float q2a = sQ2[r0];
    const float q2b = sQ2[r0 + 8];

    float l0 = 0.f, l1 = 0.f;
    float o[24][4];
    #pragma unroll
    for (int n = 0; n < 24; n++) { o[n][0]=0.f; o[n][1]=0.f; o[n][2]=0.f; o[n][3]=0.f; }

    const int src_lo = (lane & ~3) | (t4 >> 1);
    const int src_hi = src_lo + 2;
    const bool oddc  = (t4 & 1);

    for (int st = 0; st < NTOK / BC; ++st) {
        __syncthreads();   // previous tile's compute (incl. k2cur reads) done

        float* k2cur  = sK2 + ((st & 1) << 6);
        float* k2next = sK2 + (((st + 1) & 1) << 6);
        if (tid < 64) k2next[tid] = 0.f;   // read finished last iter; atomics start next iter

        // ---- K/V tile -> fragment-major smem + k^2 ----
        const float* kptr = qkv + ((size_t)b * NTOK + st * BC) * (3 * DIMC) + DIMC;
        const float* vptr = kptr + DIMC;
        for (int idx = tid * 4; idx < BC * DIMC; idx += NTHREADS * 4) {
            int r = idx / DIMC, c = idx - r * DIMC;
            float4 kk4 = *(const float4*)(kptr + (size_t)r * (3 * DIMC) + c);
            float k0 = f2tff(kk4.x * SCALE), k1 = f2tff(kk4.y * SCALE);
            float k2e = f2tff(kk4.z * SCALE), k3 = f2tff(kk4.w * SCALE);
            {
                int n = r >> 3, gk = r & 7, kc = c >> 3, chalf = (c >> 2) & 1;
                int slot = ((n & 1) << 1) | chalf;
                int swz = kc & 7;
                float* bp = sKf + (kc * 4 + (n >> 1)) * 128 + slot;
                int L = gk << 2;
                bp[((L + 0) ^ swz) << 2] = k0;
                bp[((L + 1) ^ swz) << 2] = k1;
                bp[((L + 2) ^ swz) << 2] = k2e;
                bp[((L + 3) ^ swz) << 2] = k3;
            }
            float part = k0*k0 + k1*k1 + k2e*k2e + k3*k3;
            part += __shfl_xor_sync(0xffffffffu, part, 1);
            part += __shfl_xor_sync(0xffffffffu, part, 2);
            if ((lane & 3) == 0) atomicAdd(&k2cur[r], part);

            float4 vv4 = *(const float4*)(vptr + (size_t)r * (3 * DIMC) + c);
            float v0 = f2tff(vv4.x), v1 = f2tff(vv4.y);
            float v2v = f2tff(vv4.z), v3v = f2tff(vv4.w);
            {
                int kcv = r >> 3, t4v = r & 3, rhalf = (r >> 2) & 1;
                int nn = c >> 3, npv = nn >> 1;
                int slotv = ((nn & 1) << 1) | rhalf;
                int swzv = npv & 7;
                float* vp = sVf + (kcv * 12 + npv) * 128 + slotv;
                int Lb = ((c & 7) << 2) | t4v;           // component i -> Lb + 4i (g increments)
                vp[((Lb + 0)  ^ swzv) << 2] = v0;
                vp[((Lb + 4)  ^ swzv) << 2] = v1;
                vp[((Lb + 8)  ^ swzv) << 2] = v2v;
                vp[((Lb + 12) ^ swzv) << 2] = v3v;
            }
        }
        __syncthreads();

        // ---- S = Q K^T (per warp: 16 x 64), all fragment loads are LDS.128 ----
        float sacc[8][4];
        #pragma unroll
        for (int n = 0; n < 8; n++) { sacc[n][0]=0.f; sacc[n][1]=0.f; sacc[n][2]=0.f; sacc[n][3]=0.f; }

        #pragma unroll
        for (int kc = 0; kc < 24; kc++) {
            int swz = kc & 7;
            const float4 av = *(const float4*)(sQf + (warp * 24 + kc) * 128 + ((lane ^ swz) << 2));
            uint32_t a0 = fu(av.x), a1 = fu(av.y), a2 = fu(av.z), a3 = fu(av.w);
            #pragma unroll
            for (int np = 0; np < 4; np++) {
                const float4 bv = *(const float4*)(sKf + (kc * 4 + np) * 128 + ((lane ^ swz) << 2));
                mma8(sacc[2*np],   a0, a1, a2, a3, fu(bv.x), fu(bv.y));
                mma8(sacc[2*np+1], a0, a1, a2, a3, fu(bv.z), fu(bv.w));
            }
        }

        // ---- logits -> p (no max tracking: logits in [-4, 0]) + PV MMA ----
        #pragma unroll
        for (int n = 0; n < 8; n++) {
            float2 k2 = *(const float2*)(k2cur + n * 8 + 2 * t4);
            float ta = q2a + k2.x, tb = q2a + k2.y;
            float tc = q2b + k2.x, td = q2b + k2.y;
            float d0 = fmaxf(fmaf(sacc[n][0], -2.f, ta), 0.f);
            float d1 = fmaxf(fmaf(sacc[n][1], -2.f, tb), 0.f);
            float d2 = fmaxf(fmaf(sacc[n][2], -2.f, tc), 0.f);
            float d3 = fmaxf(fmaf(sacc[n][3], -2.f, td), 0.f);
            float p0 = __expf(-sqrt_approx(d0));
            float p1 = __expf(-sqrt_approx(d1));
            float p2 = __expf(-sqrt_approx(d2));
            float p3 = __expf(-sqrt_approx(d3));
            l0 += p0 + p1; l1 += p2 + p3;

            // C-layout -> A-layout re-fragmentation
            float v0 = __shfl_sync(0xffffffffu, p0, src_lo);
            float v1 = __shfl_sync(0xffffffffu, p1, src_lo);
            float w0 = __shfl_sync(0xffffffffu, p0, src_hi);
            float w1 = __shfl_sync(0xffffffffu, p1, src_hi);
            float x0 = __shfl_sync(0xffffffffu, p2, src_lo);
            float x1 = __shfl_sync(0xffffffffu, p3, src_lo);
            float y0 = __shfl_sync(0xffffffffu, p2, src_hi);
            float y1 = __shfl_sync(0xffffffffu, p3, src_hi);
            uint32_t pa0 = fu(f2tff(oddc ? v1 : v0));
            uint32_t pa1 = fu(f2tff(oddc ? x1 : x0));
            uint32_t pa2 = fu(f2tff(oddc ? w1 : w0));
            uint32_t pa3 = fu(f2tff(oddc ? y1 : y0));

            #pragma unroll
            for (int np = 0; np < 12; np++) {
                int swzv = np & 7;
                const float4 bv = *(const float4*)(sVf + (n * 12 + np) * 128 + ((lane ^ swzv) << 2));
                mma8(o[2*np],   pa0, pa1, pa2, pa3, fu(bv.x), fu(bv.y));
                mma8(o[2*np+1], pa0, pa1, pa2, pa3, fu(bv.z), fu(bv.w));
            }
        }
    }

    // ---- epilogue: reduce l across the quad, normalize, write ----
    l0 += __shfl_xor_sync(0xffffffffu, l0, 1);
    l0 += __shfl_xor_sync(0xffffffffu, l0, 2);
    l1 += __shfl_xor_sync(0xffffffffu, l1, 1);
    l1 += __shfl_xor_sync(0xffffffffu, l1, 2);
    float il0 = 1.f / l0, il1 = 1.f / l1;
    size_t orow0 = ((size_t)b * NTOK + q0 + r0) * DIMC;
    size_t orow1 = orow0 + (size_t)8 * DIMC;
    #pragma unroll
    for (int n = 0; n < 24; n++) {
        int col = n * 8 + 2 * t4;
        float2 u0 = make_float2(o[n][0] * il0, o[n][1] * il0);
        float2 u1 = make_float2(o[n][2] * il1, o[n][3] * il1);
        *(float2*)(out + orow0 + col) = u0;
        *(float2*)(out + orow1 + col) = u1;
    }
}

extern "C" void kernel_launch(void* const* d_in, const int* in_sizes, int n_in,
                              void* d_out, int out_size) {
    const float* qkv = (const float*)d_in[0];
    float* out = (float*)d_out;
    cudaFuncSetAttribute(qkv_l2attn_kernel,
                         cudaFuncAttributeMaxDynamicSharedMemorySize, SMEM_BYTES);
    dim3 grid(NTOK / BR, NB);
    qkv_l2attn_kernel<<<grid, NTHREADS, SMEM_BYTES>>>(qkv, out);
}

// round 5
// speedup vs baseline: 3.0273x; 3.0273x over previous
#include <cuda_runtime.h>
#include <cstdint>
#include <cstddef>

#define DIMC 192
#define ROWSTRIDE 576            /* 3*DIMC */
#define NB   8
#define NTOK 4096
#define BR   128
#define BC   32
#define NTILES (NTOK / BC)
#define LDQK 196                 /* % 32 == 4: conflict-free Q/K fragment loads */
#define LDV  200                 /* % 32 == 8: conflict-free V fragment loads   */
#define NTHREADS 256
#define NEG_SCALE_LOG2E (-0.104117549f)   /* -(192^-0.5) * log2(e) */

// ---- smem layout in floats ----
#define SQ_OFF   0
#define SQ_SZ    (BR * LDQK)              /* 25088 */
#define SK_OFF   (SQ_OFF + SQ_SZ)
#define SK_SZ    (BC * LDQK)              /* 6272  */
#define SV_OFF   (SK_OFF + 2 * SK_SZ)
#define SV_SZ    (BC * LDV)               /* 6400  */
#define SK2_OFF  (SV_OFF + 2 * SV_SZ)     /* 2 x 32 */
#define SQ2_OFF  (SK2_OFF + 64)           /* 128    */
#define SMEM_FLOATS (SQ2_OFF + 128)
#define SMEM_BYTES  (SMEM_FLOATS * 4)     /* 202,496 B */

__device__ __forceinline__ uint32_t fu(float f) { return __float_as_uint(f); }
__device__ __forceinline__ float maskf(float x) {
    return __uint_as_float(__float_as_uint(x) & 0xFFFFE000u);   /* tf32 truncation */
}
__device__ __forceinline__ float sqrt_approx(float x) {
    float r; asm("sqrt.approx.f32 %0, %1;" : "=f"(r) : "f"(x)); return r;
}
__device__ __forceinline__ float ex2_approx(float x) {
    float r; asm("ex2.approx.f32 %0, %1;" : "=f"(r) : "f"(x)); return r;
}
__device__ __forceinline__ uint32_t smem_u32(const void* p) {
    uint32_t a;
    asm("{ .reg .u64 t; cvta.to.shared.u64 t, %1; cvt.u32.u64 %0, t; }" : "=r"(a) : "l"(p));
    return a;
}

#define CP_ASYNC16(dst, src) \
    asm volatile("cp.async.cg.shared.global [%0], [%1], 16;" :: "r"(dst), "l"(src) : "memory")
#define CP_COMMIT() asm volatile("cp.async.commit_group;" ::: "memory")
#define CP_WAIT0()  asm volatile("cp.async.wait_group 0;" ::: "memory")

__device__ __forceinline__ void mma8(float* c,
        uint32_t a0, uint32_t a1, uint32_t a2, uint32_t a3,
        uint32_t b0, uint32_t b1) {
    asm volatile("mma.sync.aligned.m16n8k8.row.col.f32.tf32.tf32.f32 "
        "{%0,%1,%2,%3}, {%4,%5,%6,%7}, {%8,%9}, {%0,%1,%2,%3};"
        : "+f"(c[0]), "+f"(c[1]), "+f"(c[2]), "+f"(c[3])
        : "r"(a0), "r"(a1), "r"(a2), "r"(a3), "r"(b0), "r"(b1));
}

// prefetch raw K/V for tile st into buffer (st & 1)
__device__ __forceinline__ void prefetch_kv(uint32_t smb, const float* __restrict__ qkv,
                                            int b, int st) {
    const int tid = threadIdx.x;
    const int buf = st & 1;
    const float* base = qkv + ((size_t)(b * NTOK + st * BC)) * ROWSTRIDE + DIMC;
    const uint32_t kd = smb + (SK_OFF + buf * SK_SZ) * 4;
    const uint32_t vd = smb + (SV_OFF + buf * SV_SZ) * 4;
    #pragma unroll
    for (int i = 0; i < 6; i++) {
        int idx = tid + i * NTHREADS;          // 0..1535 over 32 rows x 48 float4
        int r = idx / 48, c = (idx - r * 48) * 4;
        CP_ASYNC16(kd + (uint32_t)(r * LDQK + c) * 4, base + (size_t)r * ROWSTRIDE + c);
    }
    #pragma unroll
    for (int i = 0; i < 6; i++) {
        int idx = tid + i * NTHREADS;
        int r = idx / 48, c = (idx - r * 48) * 4;
        CP_ASYNC16(vd + (uint32_t)(r * LDV + c) * 4, base + (size_t)r * ROWSTRIDE + DIMC + c);
    }
}

__global__ void __launch_bounds__(NTHREADS, 1)
qkv_l2attn_kernel(const float* __restrict__ qkv, float* __restrict__ out)
{
    extern __shared__ float sm[];
    float* sQ  = sm + SQ_OFF;
    float* sK2 = sm + SK2_OFF;
    float* sQ2 = sm + SQ2_OFF;
    const uint32_t smb = smem_u32(sm);

    const int tid  = threadIdx.x;
    const int warp = tid >> 5;
    const int lane = tid & 31;
    const int g    = lane >> 2;
    const int t4   = lane & 3;

    const int b  = blockIdx.y;
    const int q0 = blockIdx.x * BR;

    // ---- prologue: start K/V tile 0 prefetch, then load Q raw ----
    prefetch_kv(smb, qkv, b, 0);
    CP_COMMIT();

    const float* qptr = qkv + ((size_t)(b * NTOK + q0)) * ROWSTRIDE;
    for (int idx = tid * 4; idx < BR * DIMC; idx += NTHREADS * 4) {
        int r = idx / DIMC, c = idx - r * DIMC;
        *(float4*)(sQ + r * LDQK + c) = *(const float4*)(qptr + (size_t)r * ROWSTRIDE + c);
    }
    __syncthreads();
    {   // q2 from masked values: 2 threads per row
        int r = tid >> 1, half = tid & 1;
        const float* p = sQ + r * LDQK + half * 96;
        float s = 0.f;
        #pragma unroll
        for (int i = 0; i < 24; i++) {
            float4 v = *(const float4*)(p + i * 4);
            float x0 = maskf(v.x), x1 = maskf(v.y), x2 = maskf(v.z), x3 = maskf(v.w);
            s += x0*x0 + x1*x1 + x2*x2 + x3*x3;
        }
        s += __shfl_xor_sync(0xffffffffu, s, 1);
        if (half == 0) sQ2[r] = s;
    }
    __syncthreads();

    const int r0 = warp * 16 + g;
    const float q2a = sQ2[r0];
    const float q2b = sQ2[r0 + 8];

    float l0 = 0.f, l1 = 0.f;
    float o[24][4];
    #pragma unroll
    for (int n = 0; n < 24; n++) { o[n][0]=0.f; o[n][1]=0.f; o[n][2]=0.f; o[n][3]=0.f; }

    const int src_lo = (lane & ~3) | (t4 >> 1);
    const int src_hi = src_lo + 2;
    const bool oddc  = (t4 & 1);

    for (int st = 0; st < NTILES; ++st) {
        const int buf = st & 1;
        float* sK = sm + SK_OFF + buf * SK_SZ;
        float* sV = sm + SV_OFF + buf * SV_SZ;
        float* k2c = sK2 + buf * 32;

        CP_WAIT0();
        __syncthreads();                 // tile st data visible; compute(st-1) done

        if (st + 1 < NTILES) { prefetch_kv(smb, qkv, b, st + 1); CP_COMMIT(); }

        {   // k2 for this tile: 8 threads per key row
            int r = tid >> 3, seg = tid & 7;
            const float* p = sK + r * LDQK + seg * 24;
            float s = 0.f;
            #pragma unroll
            for (int i = 0; i < 6; i++) {
                float4 v = *(const float4*)(p + i * 4);
                float x0 = maskf(v.x), x1 = maskf(v.y), x2 = maskf(v.z), x3 = maskf(v.w);
                s += x0*x0 + x1*x1 + x2*x2 + x3*x3;
            }
            s += __shfl_xor_sync(0xffffffffu, s, 1);
            s += __shfl_xor_sync(0xffffffffu, s, 2);
            s += __shfl_xor_sync(0xffffffffu, s, 4);
            if (seg == 0) k2c[r] = s;
        }
        __syncthreads();

        // ---- S = Q K^T (per warp: 16 x 32) ----
        float sacc[4][4];
        #pragma unroll
        for (int n = 0; n < 4; n++) { sacc[n][0]=0.f; sacc[n][1]=0.f; sacc[n][2]=0.f; sacc[n][3]=0.f; }

        #pragma unroll
        for (int kc = 0; kc < 24; kc++) {
            const int kk = kc * 8;
            uint32_t a0 = fu(sQ[(r0)     * LDQK + kk     + t4]);
            uint32_t a1 = fu(sQ[(r0 + 8) * LDQK + kk     + t4]);
            uint32_t a2 = fu(sQ[(r0)     * LDQK + kk + 4 + t4]);
            uint32_t a3 = fu(sQ[(r0 + 8) * LDQK + kk + 4 + t4]);
            #pragma unroll
            for (int n = 0; n < 4; n++) {
                uint32_t b0 = fu(sK[(n * 8 + g) * LDQK + kk     + t4]);
                uint32_t b1 = fu(sK[(n * 8 + g) * LDQK + kk + 4 + t4]);
                mma8(sacc[n], a0, a1, a2, a3, b0, b1);
            }
        }

        // ---- softmax chunk + PV (per 8-key group) ----
        #pragma unroll
        for (int n = 0; n < 4; n++) {
            float2 k2 = *(const float2*)(k2c + n * 8 + 2 * t4);
            float d0 = fmaxf(fmaf(sacc[n][0], -2.f, q2a + k2.x), 0.f);
            float d1 = fmaxf(fmaf(sacc[n][1], -2.f, q2a + k2.y), 0.f);
            float d2 = fmaxf(fmaf(sacc[n][2], -2.f, q2b + k2.x), 0.f);
            float d3 = fmaxf(fmaf(sacc[n][3], -2.f, q2b + k2.y), 0.f);
            float p0 = maskf(ex2_approx(sqrt_approx(d0) * NEG_SCALE_LOG2E));
            float p1 = maskf(ex2_approx(sqrt_approx(d1) * NEG_SCALE_LOG2E));
            float p2 = maskf(ex2_approx(sqrt_approx(d2) * NEG_SCALE_LOG2E));
            float p3 = maskf(ex2_approx(sqrt_approx(d3) * NEG_SCALE_LOG2E));
            l0 += p0 + p1; l1 += p2 + p3;

            // C-layout -> A-layout re-fragmentation
            float v0 = __shfl_sync(0xffffffffu, p0, src_lo);
            float v1 = __shfl_sync(0xffffffffu, p1, src_lo);
            float w0 = __shfl_sync(0xffffffffu, p0, src_hi);
            float w1 = __shfl_sync(0xffffffffu, p1, src_hi);
            float x0 = __shfl_sync(0xffffffffu, p2, src_lo);
            float x1 = __shfl_sync(0xffffffffu, p3, src_lo);
            float y0 = __shfl_sync(0xffffffffu, p2, src_hi);
            float y1 = __shfl_sync(0xffffffffu, p3, src_hi);
            uint32_t pa0 = fu(oddc ? v1 : v0);
            uint32_t pa1 = fu(oddc ? x1 : x0);
            uint32_t pa2 = fu(oddc ? w1 : w0);
            uint32_t pa3 = fu(oddc ? y1 : y0);

            const int kk = n * 8;
            #pragma unroll
            for (int nn = 0; nn < 24; nn++) {
                uint32_t b0 = fu(sV[(kk +     t4) * LDV + nn * 8 + g]);
                uint32_t b1 = fu(sV[(kk + 4 + t4) * LDV + nn * 8 + g]);
                mma8(o[nn], pa0, pa1, pa2, pa3, b0, b1);
            }
        }
    }

    // ---- epilogue ----
    l0 += __shfl_xor_sync(0xffffffffu, l0, 1);
    l0 += __shfl_xor_sync(0xffffffffu, l0, 2);
    l1 += __shfl_xor_sync(0xffffffffu, l1, 1);
    l1 += __shfl_xor_sync(0xffffffffu, l1, 2);
    float il0 = 1.f / l0, il1 = 1.f / l1;
    size_t orow0 = ((size_t)(b * NTOK + q0 + r0)) * DIMC;
    size_t orow1 = orow0 + (size_t)8 * DIMC;
    #pragma unroll
    for (int n = 0; n < 24; n++) {
        int col = n * 8 + 2 * t4;
        *(float2*)(out + orow0 + col) = make_float2(o[n][0] * il0, o[n][1] * il0);
        *(float2*)(out + orow1 + col) = make_float2(o[n][2] * il1, o[n][3] * il1);
    }
}

extern "C" void kernel_launch(void* const* d_in, const int* in_sizes, int n_in,
                              void* d_out, int out_size) {
    const float* qkv = (const float*)d_in[0];
    float* out = (float*)d_out;
    cudaFuncSetAttribute(qkv_l2attn_kernel,
                         cudaFuncAttributeMaxDynamicSharedMemorySize, SMEM_BYTES);
    dim3 grid(NTOK / BR, NB);
    qkv_l2attn_kernel<<<grid, NTHREADS, SMEM_BYTES>>>(qkv, out);
}